// round 3
// baseline (speedup 1.0000x reference)
#include <cuda_runtime.h>

// SpatialTransformer: out[b,c,d,h,w] = trilinear_sample(src[b,c], (w,h,d)+flow[b,:,d,h,w])
// align_corners=True normalization cancels; padding_mode='zeros'.
//
// L1 wavefront model (R2): gather cost = loads/warp x distinct-lines/load, lines
// dominated by (z0,y0) scatter. So minimize load INSTRUCTIONS: store overlapping
// x-pairs as aligned float4 (c0[x], c1[x], c0[x+1], c1[x+1]) -> 4 LDG.128/thread.

#define Dz 160
#define Hy 192
#define Wx 160
#define Bn 2
#define Cn 2
#define HW (Hy * Wx)            // 30720
#define DHW (Dz * Hy * Wx)      // 4915200

// pair[b][s] = (c0[x], c1[x], c0[x+1c], c1[x+1c])  (x+1 clamped within row)
// 2 * 4915200 * 16B = 157 MB scratch.
__device__ float4 g_pair[Bn * DHW];

__global__ __launch_bounds__(256) void build_pairs_kernel(const float* __restrict__ src)
{
    // Each thread handles 4 consecutive voxels of one batch (rows are 160 = 4*40,
    // so a group of 4 never crosses a row boundary).
    int v = blockIdx.x * blockDim.x + threadIdx.x;
    int total = Bn * (DHW / 4);
    if (v >= total) return;
    int b = v / (DHW / 4);
    int g = v - b * (DHW / 4);
    int s = g * 4;                        // linear voxel index within batch
    int x3 = (s + 3) % Wx;                // x of last voxel in group

    const float* c0 = src + (size_t)b * Cn * DHW;
    const float* c1 = c0 + DHW;

    float4 a = *(const float4*)(c0 + s);
    float4 c = *(const float4*)(c1 + s);
    float a4, c4;
    if (x3 == Wx - 1) { a4 = a.w; c4 = c.w; }           // clamp at row end
    else             { a4 = c0[s + 4]; c4 = c1[s + 4]; }

    float4* dst = g_pair + (size_t)b * DHW + s;
    dst[0] = make_float4(a.x, c.x, a.y, c.y);
    dst[1] = make_float4(a.y, c.y, a.z, c.z);
    dst[2] = make_float4(a.z, c.z, a.w, c.w);
    dst[3] = make_float4(a.w, c.w, a4, c4);
}

__global__ __launch_bounds__(256) void warp3d_kernel(
    const float* __restrict__ flow,
    float* __restrict__ out)
{
    int idx = blockIdx.x * blockDim.x + threadIdx.x;
    if (idx >= Bn * DHW) return;

    int b = idx / DHW;
    int s = idx - b * DHW;
    int w = s % Wx;
    int t = s / Wx;
    int h = t % Hy;
    int d = t / Hy;

    const float* fb = flow + (size_t)b * 3 * DHW;
    float x = (float)w + __ldg(fb + s);
    float y = (float)h + __ldg(fb + s + DHW);
    float z = (float)d + __ldg(fb + s + 2 * DHW);

    float x0f = floorf(x), y0f = floorf(y), z0f = floorf(z);
    float fx = x - x0f, fy = y - y0f, fz = z - z0f;
    int x0 = (int)x0f, y0 = (int)y0f, z0 = (int)z0f;
    int y1 = y0 + 1, z1 = z0 + 1;

    // x-pair weights: pair load at clamped x gives (lo = v[x0c], hi = v[x0c+1c]).
    // Normal case x0 in [0,W): lo gets 1-fx, hi gets fx (0 if x1 == W).
    // x0 == -1: needed value v[0] sits in lo slot -> lo gets fx, hi 0.
    float wlo = (x0 >= 0 && x0 < Wx) ? (1.0f - fx) : ((x0 == -1) ? fx : 0.0f);
    float whi = (x0 >= 0 && x0 + 1 < Wx) ? fx : 0.0f;

    float wy0 = (y0 >= 0 && y0 < Hy) ? (1.0f - fy) : 0.0f;
    float wy1 = (y1 >= 0 && y1 < Hy) ? fy          : 0.0f;
    float wz0 = (z0 >= 0 && z0 < Dz) ? (1.0f - fz) : 0.0f;
    float wz1 = (z1 >= 0 && z1 < Dz) ? fz          : 0.0f;

    int xp  = min(max(x0, 0), Wx - 1);
    int y0c = min(max(y0, 0), Hy - 1);
    int y1c = min(max(y1, 0), Hy - 1);
    int z0c = min(max(z0, 0), Dz - 1);
    int z1c = min(max(z1, 0), Dz - 1);

    const float4* pb = g_pair + (size_t)b * DHW;

    float4 P00 = __ldg(pb + z0c * HW + y0c * Wx + xp);
    float4 P01 = __ldg(pb + z0c * HW + y1c * Wx + xp);
    float4 P10 = __ldg(pb + z1c * HW + y0c * Wx + xp);
    float4 P11 = __ldg(pb + z1c * HW + y1c * Wx + xp);

    float w00 = wz0 * wy0, w01 = wz0 * wy1;
    float w10 = wz1 * wy0, w11 = wz1 * wy1;

    // acc = wlo * sum(wzy * lo) + whi * sum(wzy * hi), per channel
    float lo0 = w00 * P00.x + w01 * P01.x + w10 * P10.x + w11 * P11.x;
    float lo1 = w00 * P00.y + w01 * P01.y + w10 * P10.y + w11 * P11.y;
    float hi0 = w00 * P00.z + w01 * P01.z + w10 * P10.z + w11 * P11.z;
    float hi1 = w00 * P00.w + w01 * P01.w + w10 * P10.w + w11 * P11.w;

    float acc0 = wlo * lo0 + whi * hi0;
    float acc1 = wlo * lo1 + whi * hi1;

    float* ob = out + (size_t)b * Cn * DHW;
    ob[s] = acc0;
    ob[DHW + s] = acc1;
}

extern "C" void kernel_launch(void* const* d_in, const int* in_sizes, int n_in,
                              void* d_out, int out_size) {
    const float* src  = (const float*)d_in[0];
    const float* flow = (const float*)d_in[1];
    float* out = (float*)d_out;

    int threads = 256;
    int total_p = Bn * (DHW / 4);
    build_pairs_kernel<<<(total_p + threads - 1) / threads, threads>>>(src);

    int total = Bn * DHW;
    warp3d_kernel<<<(total + threads - 1) / threads, threads>>>(flow, out);
}